// round 15
// baseline (speedup 1.0000x reference)
#include <cuda_runtime.h>
#include <math_constants.h>

// RandomFeatures, round 15: unit = WHOLE k (NQ=1). One warp computes all of
// one k's conv+reductions in registers and writes out directly -> no scratch,
// no cross-warp combine, no finalize kernel. Unit sizes are near-uniform
// (time ~ ol*klen, independent of d), so 4096 units over 4440 warps balance.
// Main loop identical to the r6 champion (reload conv_block, 8/4/2/1 chain).
// lane = batch; xs transposed [(HALO+T+HALO)][33] in shared; warp-uniform row
// index => bank = lane => conflict-free.

#define MAX_KLEN 11
#define WARPS_PER_CTA 15
#define XPITCH 33
#define HALO 128
#define BGMAX 4

__device__ int g_ctr[BGMAX];            // work counter (self-reset)
__device__ int g_done[BGMAX];           // CTA done counter (self-reset)

template<int KLEN, int NB>
__device__ __forceinline__ void conv_block(
    const float* __restrict__ p,     // &xs[(HALO+base)*XPITCH + lane]
    int dp,                          // d * XPITCH
    const float* __restrict__ w, float bs,
    float& mx, float& cnt)
{
    float Y[NB + KLEN - 1];
#pragma unroll
    for (int t = 0; t < NB + KLEN - 1; t++) Y[t] = p[t * dp];
#pragma unroll
    for (int i = 0; i < NB; i++) {
        float a = bs;
#pragma unroll
        for (int j = 0; j < KLEN; j++) a = fmaf(w[j], Y[i + j], a);
        mx = fmaxf(mx, a);
        cnt += (a > 0.0f) ? 1.0f : 0.0f;
    }
}

template<int KLEN>
__device__ __forceinline__ void conv_range(
    const float* __restrict__ xsl,   // xs + lane
    int r, int pd, int mhi, int d, int dp,
    const float* __restrict__ w, float bs,
    float& mx, float& cnt)
{
    int m0 = 0;
    const float* p = xsl + (HALO + r - pd) * XPITCH;
    for (; m0 + 8 <= mhi; m0 += 8) {
        conv_block<KLEN, 8>(p, dp, w, bs, mx, cnt);
        p += 8 * dp;
    }
    if (m0 + 4 <= mhi) { conv_block<KLEN, 4>(p, dp, w, bs, mx, cnt); m0 += 4; p += 4 * dp; }
    if (m0 + 2 <= mhi) { conv_block<KLEN, 2>(p, dp, w, bs, mx, cnt); m0 += 2; p += 2 * dp; }
    if (m0 < mhi)      { conv_block<KLEN, 1>(p, dp, w, bs, mx, cnt); }
}

template<int KLEN>
__device__ __forceinline__ void process_k(
    const float* __restrict__ xsl, int d, int pd, int ol,
    const float* __restrict__ w, float bs, float& mx, float& cnt)
{
    const int dp = d * XPITCH;
    const int q0 = (ol - 1) / d;                 // one division per k
    const int rr = (ol - 1) - q0 * d;
    for (int r = 0; r < d; r++) {
        const int M = (r <= rr) ? q0 + 1 : q0;   // = ceil((ol-r)/d)
        conv_range<KLEN>(xsl, r, pd, M, d, dp, w, bs, mx, cnt);
    }
}

// Safe fallback for parameters outside the halo guarantee (not expected).
template<int KLEN>
__device__ __forceinline__ void process_k_safe(
    const float* __restrict__ xsl, int d, int pd, int ol, int T,
    const float* __restrict__ w, float bs, float& mx, float& cnt)
{
    for (int p = 0; p < ol; p++) {
        float a = bs;
#pragma unroll
        for (int j = 0; j < KLEN; j++) {
            const long long ix = (long long)p - pd + (long long)j * d;
            const int ixc = (int)min(max(ix, 0LL), (long long)(T - 1));
            float v = xsl[(HALO + ixc) * XPITCH];
            a = fmaf(w[j], (ix >= 0 && ix < T) ? v : 0.0f, a);
        }
        mx = fmaxf(mx, a);
        cnt += (a > 0.0f) ? 1.0f : 0.0f;
    }
}

__global__ void __launch_bounds__(32 * WARPS_PER_CTA, 2)
rf_main(const float* __restrict__ x,
        const float* __restrict__ w,
        const float* __restrict__ bias,
        const int*   __restrict__ dil,
        const int*   __restrict__ padr,
        const int*   __restrict__ olen,
        float* __restrict__ out,
        int B, int T, int K)
{
    extern __shared__ float xs[];                 // [(HALO+T+HALO)][XPITCH]
    const int lane = threadIdx.x & 31;
    const int warp = threadIdx.x >> 5;
    const int bg   = blockIdx.y;
    const int b0   = bg * 32;
    const int nb   = min(32, B - b0);

    // Transposed fill with zero halos: coalesced LDG, conflict-free STS (33 odd).
    for (int bb = warp; bb < 32; bb += WARPS_PER_CTA) {
        const int bsafe = min(bb, nb - 1);
        for (int t = lane; t < HALO; t += 32) {
            xs[t * XPITCH + bb] = 0.0f;
            xs[(HALO + T + t) * XPITCH + bb] = 0.0f;
        }
        for (int t = lane; t < T; t += 32) {
            float v = x[(size_t)(b0 + bsafe) * T + t];
            xs[(HALO + t) * XPITCH + bb] = (bb < nb) ? v : 0.0f;
        }
    }
    __syncthreads();

    const float* xsl = xs + lane;

    for (;;) {
        int k = 0;
        if (lane == 0) k = atomicAdd(&g_ctr[bg], 1);
        k = __shfl_sync(0xFFFFFFFFu, k, 0);
        if (k >= K) break;

        const int   d  = dil[k];
        const int   pd = padr[k];
        const int   ol = olen[k];
        const float bv = bias[k];

        float wreg[MAX_KLEN];
#pragma unroll
        for (int j = 0; j < MAX_KLEN; j++)
            wreg[j] = __ldg(&w[(size_t)k * MAX_KLEN + j]);

        float mx  = -CUDART_INF_F;
        float cnt = 0.0f;

        // klen inference: taps >= klen are exactly zero by construction.
        const int klen = (wreg[9] != 0.0f || wreg[10] != 0.0f) ? 11
                       : (wreg[7] != 0.0f || wreg[8] != 0.0f) ? 9 : 7;
        const bool safe = (d >= 1) && (pd < HALO) &&
                          ((ol - 1) - pd + (long long)(klen - 1) * d < T + HALO);

        if (safe) {
            if (klen == 11)      process_k<11>(xsl, d, pd, ol, wreg, bv, mx, cnt);
            else if (klen == 9)  process_k<9>(xsl, d, pd, ol, wreg, bv, mx, cnt);
            else                 process_k<7>(xsl, d, pd, ol, wreg, bv, mx, cnt);
        } else if (d >= 1) {
            if (klen == 11)      process_k_safe<11>(xsl, d, pd, ol, T, wreg, bv, mx, cnt);
            else if (klen == 9)  process_k_safe<9>(xsl, d, pd, ol, T, wreg, bv, mx, cnt);
            else                 process_k_safe<7>(xsl, d, pd, ol, T, wreg, bv, mx, cnt);
        }

        // Whole k done by this warp: write result directly. lane = batch.
        if (lane < nb) {
            float* o = out + (size_t)(b0 + lane) * 2 * K + 2 * k;
            o[0] = mx;
            o[1] = cnt / (float)ol;
        }
    }

    // Last CTA per batch group resets the work counter for the next replay.
    __syncthreads();
    if (threadIdx.x == 0) {
        int dn = atomicAdd(&g_done[bg], 1);
        if (dn == (int)gridDim.x - 1) {
            g_ctr[bg]  = 0;
            g_done[bg] = 0;
        }
    }
}

extern "C" void kernel_launch(void* const* d_in, const int* in_sizes, int n_in,
                              void* d_out, int out_size) {
    const float* x    = (const float*)d_in[0];
    const float* w    = (const float*)d_in[1];
    const float* bias = (const float*)d_in[2];
    const int*   dil  = (const int*)d_in[3];
    const int*   padr = (const int*)d_in[4];
    const int*   olen = (const int*)d_in[5];
    float* out = (float*)d_out;

    const int K = in_sizes[2];                 // bias element count
    const int B = out_size / (2 * K);
    const int T = in_sizes[0] / B;
    const int nbg = (B + 31) / 32;             // batch groups (<= BGMAX)

    const size_t smem = (size_t)(2 * HALO + T) * XPITCH * sizeof(float);
    cudaFuncSetAttribute(rf_main,
                         cudaFuncAttributeMaxDynamicSharedMemorySize,
                         (int)smem);

    // 2 CTAs/SM x 148 SMs persistent, split across batch groups.
    int ctas_per_bg = (296 + nbg - 1) / nbg;
    dim3 grid(ctas_per_bg, nbg);
    rf_main<<<grid, 32 * WARPS_PER_CTA, smem>>>(x, w, bias, dil, padr, olen,
                                                out, B, T, K);
}

// round 16
// speedup vs baseline: 1.0032x; 1.0032x over previous
#include <cuda_runtime.h>
#include <math_constants.h>

// RandomFeatures, round 16: r15 whole-k units + clamped-block fallback.
// The zero halos mean OOB taps read 0 via simple index CLAMP (no masks), so
// the "unsafe" path (pad > HALO) is now the same blocked sliding-window kernel
// with clamped row indices (~1.4x fast path instead of ~3.5x guarded scalar).
// This removes the whole-k long poles that made r15 slower than r6.
// lane = batch; xs transposed [(HALO+T+HALO)][33] in shared; warp-uniform row
// index => bank = lane => conflict-free. One warp per k, direct out write.

#define MAX_KLEN 11
#define WARPS_PER_CTA 15
#define XPITCH 33
#define HALO 128
#define BGMAX 4

__device__ int g_ctr[BGMAX];            // work counter (self-reset)
__device__ int g_done[BGMAX];           // CTA done counter (self-reset)

// ---------- fast path (all taps within halo bounds) ----------
template<int KLEN, int NB>
__device__ __forceinline__ void conv_block(
    const float* __restrict__ p,     // &xs[(HALO+base)*XPITCH + lane]
    int dp,                          // d * XPITCH
    const float* __restrict__ w, float bs,
    float& mx, float& cnt)
{
    float Y[NB + KLEN - 1];
#pragma unroll
    for (int t = 0; t < NB + KLEN - 1; t++) Y[t] = p[t * dp];
#pragma unroll
    for (int i = 0; i < NB; i++) {
        float a = bs;
#pragma unroll
        for (int j = 0; j < KLEN; j++) a = fmaf(w[j], Y[i + j], a);
        mx = fmaxf(mx, a);
        cnt += (a > 0.0f) ? 1.0f : 0.0f;
    }
}

template<int KLEN>
__device__ __forceinline__ void conv_range(
    const float* __restrict__ xsl,   // xs + lane
    int r, int pd, int mhi, int d, int dp,
    const float* __restrict__ w, float bs,
    float& mx, float& cnt)
{
    int m0 = 0;
    const float* p = xsl + (HALO + r - pd) * XPITCH;
    for (; m0 + 8 <= mhi; m0 += 8) {
        conv_block<KLEN, 8>(p, dp, w, bs, mx, cnt);
        p += 8 * dp;
    }
    if (m0 + 4 <= mhi) { conv_block<KLEN, 4>(p, dp, w, bs, mx, cnt); m0 += 4; p += 4 * dp; }
    if (m0 + 2 <= mhi) { conv_block<KLEN, 2>(p, dp, w, bs, mx, cnt); m0 += 2; p += 2 * dp; }
    if (m0 < mhi)      { conv_block<KLEN, 1>(p, dp, w, bs, mx, cnt); }
}

template<int KLEN>
__device__ __forceinline__ void process_k(
    const float* __restrict__ xsl, int d, int pd, int ol,
    const float* __restrict__ w, float bs, float& mx, float& cnt)
{
    const int dp = d * XPITCH;
    const int q0 = (ol - 1) / d;                 // one division per k
    const int rr = (ol - 1) - q0 * d;
    for (int r = 0; r < d; r++) {
        const int M = (r <= rr) ? q0 + 1 : q0;   // = ceil((ol-r)/d)
        conv_range<KLEN>(xsl, r, pd, M, d, dp, w, bs, mx, cnt);
    }
}

// ---------- clamped path (pad > HALO): clamp row into the zero halos ----------
template<int KLEN, int NB>
__device__ __forceinline__ void conv_block_c(
    const float* __restrict__ xsl, int row0, int d, int rmax,
    const float* __restrict__ w, float bs,
    float& mx, float& cnt)
{
    float Y[NB + KLEN - 1];
#pragma unroll
    for (int t = 0; t < NB + KLEN - 1; t++) {
        int rr = row0 + t * d;
        rr = min(max(rr, 0), rmax);              // lands in zero halo if OOB
        Y[t] = xsl[rr * XPITCH];
    }
#pragma unroll
    for (int i = 0; i < NB; i++) {
        float a = bs;
#pragma unroll
        for (int j = 0; j < KLEN; j++) a = fmaf(w[j], Y[i + j], a);
        mx = fmaxf(mx, a);
        cnt += (a > 0.0f) ? 1.0f : 0.0f;
    }
}

template<int KLEN>
__device__ __forceinline__ void conv_range_c(
    const float* __restrict__ xsl,
    int r, int pd, int mhi, int d, int rmax,
    const float* __restrict__ w, float bs,
    float& mx, float& cnt)
{
    int m0 = 0;
    int row0 = HALO + r - pd;
    for (; m0 + 8 <= mhi; m0 += 8) {
        conv_block_c<KLEN, 8>(xsl, row0, d, rmax, w, bs, mx, cnt);
        row0 += 8 * d;
    }
    if (m0 + 4 <= mhi) { conv_block_c<KLEN, 4>(xsl, row0, d, rmax, w, bs, mx, cnt); m0 += 4; row0 += 4 * d; }
    if (m0 + 2 <= mhi) { conv_block_c<KLEN, 2>(xsl, row0, d, rmax, w, bs, mx, cnt); m0 += 2; row0 += 2 * d; }
    if (m0 < mhi)      { conv_block_c<KLEN, 1>(xsl, row0, d, rmax, w, bs, mx, cnt); }
}

template<int KLEN>
__device__ __forceinline__ void process_k_c(
    const float* __restrict__ xsl, int d, int pd, int ol, int T,
    const float* __restrict__ w, float bs, float& mx, float& cnt)
{
    const int rmax = 2 * HALO + T - 1;
    const int q0 = (ol - 1) / d;                 // one division per k
    const int rr = (ol - 1) - q0 * d;
    for (int r = 0; r < d; r++) {
        const int M = (r <= rr) ? q0 + 1 : q0;
        conv_range_c<KLEN>(xsl, r, pd, M, d, rmax, w, bs, mx, cnt);
    }
}

__global__ void __launch_bounds__(32 * WARPS_PER_CTA, 2)
rf_main(const float* __restrict__ x,
        const float* __restrict__ w,
        const float* __restrict__ bias,
        const int*   __restrict__ dil,
        const int*   __restrict__ padr,
        const int*   __restrict__ olen,
        float* __restrict__ out,
        int B, int T, int K)
{
    extern __shared__ float xs[];                 // [(HALO+T+HALO)][XPITCH]
    const int lane = threadIdx.x & 31;
    const int warp = threadIdx.x >> 5;
    const int bg   = blockIdx.y;
    const int b0   = bg * 32;
    const int nb   = min(32, B - b0);

    // Transposed fill with zero halos: coalesced LDG, conflict-free STS (33 odd).
    for (int bb = warp; bb < 32; bb += WARPS_PER_CTA) {
        const int bsafe = min(bb, nb - 1);
        for (int t = lane; t < HALO; t += 32) {
            xs[t * XPITCH + bb] = 0.0f;
            xs[(HALO + T + t) * XPITCH + bb] = 0.0f;
        }
        for (int t = lane; t < T; t += 32) {
            float v = x[(size_t)(b0 + bsafe) * T + t];
            xs[(HALO + t) * XPITCH + bb] = (bb < nb) ? v : 0.0f;
        }
    }
    __syncthreads();

    const float* xsl = xs + lane;

    for (;;) {
        int k = 0;
        if (lane == 0) k = atomicAdd(&g_ctr[bg], 1);
        k = __shfl_sync(0xFFFFFFFFu, k, 0);
        if (k >= K) break;

        const int   d  = dil[k];
        const int   pd = padr[k];
        const int   ol = olen[k];
        const float bv = bias[k];

        float wreg[MAX_KLEN];
#pragma unroll
        for (int j = 0; j < MAX_KLEN; j++)
            wreg[j] = __ldg(&w[(size_t)k * MAX_KLEN + j]);

        float mx  = -CUDART_INF_F;
        float cnt = 0.0f;

        // klen inference: taps >= klen are exactly zero by construction.
        const int klen = (wreg[9] != 0.0f || wreg[10] != 0.0f) ? 11
                       : (wreg[7] != 0.0f || wreg[8] != 0.0f) ? 9 : 7;
        // Fast path iff every touched index lies within the +-HALO zero margin.
        const bool safe = (d >= 1) && (pd < HALO) &&
                          ((ol - 1) - pd + (long long)(klen - 1) * d < T + HALO);

        if (safe) {
            if (klen == 11)      process_k<11>(xsl, d, pd, ol, wreg, bv, mx, cnt);
            else if (klen == 9)  process_k<9>(xsl, d, pd, ol, wreg, bv, mx, cnt);
            else                 process_k<7>(xsl, d, pd, ol, wreg, bv, mx, cnt);
        } else if (d >= 1) {
            if (klen == 11)      process_k_c<11>(xsl, d, pd, ol, T, wreg, bv, mx, cnt);
            else if (klen == 9)  process_k_c<9>(xsl, d, pd, ol, T, wreg, bv, mx, cnt);
            else                 process_k_c<7>(xsl, d, pd, ol, T, wreg, bv, mx, cnt);
        }

        // Whole k done by this warp: write result directly. lane = batch.
        if (lane < nb) {
            float* o = out + (size_t)(b0 + lane) * 2 * K + 2 * k;
            o[0] = mx;
            o[1] = cnt / (float)ol;
        }
    }

    // Last CTA per batch group resets the work counter for the next replay.
    __syncthreads();
    if (threadIdx.x == 0) {
        int dn = atomicAdd(&g_done[bg], 1);
        if (dn == (int)gridDim.x - 1) {
            g_ctr[bg]  = 0;
            g_done[bg] = 0;
        }
    }
}

extern "C" void kernel_launch(void* const* d_in, const int* in_sizes, int n_in,
                              void* d_out, int out_size) {
    const float* x    = (const float*)d_in[0];
    const float* w    = (const float*)d_in[1];
    const float* bias = (const float*)d_in[2];
    const int*   dil  = (const int*)d_in[3];
    const int*   padr = (const int*)d_in[4];
    const int*   olen = (const int*)d_in[5];
    float* out = (float*)d_out;

    const int K = in_sizes[2];                 // bias element count
    const int B = out_size / (2 * K);
    const int T = in_sizes[0] / B;
    const int nbg = (B + 31) / 32;             // batch groups (<= BGMAX)

    const size_t smem = (size_t)(2 * HALO + T) * XPITCH * sizeof(float);
    cudaFuncSetAttribute(rf_main,
                         cudaFuncAttributeMaxDynamicSharedMemorySize,
                         (int)smem);

    // 2 CTAs/SM x 148 SMs persistent, split across batch groups.
    int ctas_per_bg = (296 + nbg - 1) / nbg;
    dim3 grid(ctas_per_bg, nbg);
    rf_main<<<grid, 32 * WARPS_PER_CTA, smem>>>(x, w, bias, dil, padr, olen,
                                                out, B, T, K);
}

// round 17
// speedup vs baseline: 1.0620x; 1.0587x over previous
#include <cuda_runtime.h>
#include <math_constants.h>

// RandomFeatures, round 17: single kernel, two phases.
// Phase 1 = r6 champion main (NQ=4 quarter-k units, reload conv_block,
// clamped pole fallback, partials -> L2 scratch via __stcg, no fences).
// Grid-wide barrier (release add + acquire spin; safe: launch_bounds
// guarantees one resident wave). Phase 2 = in-kernel finalize: one warp per k
// combines 4 quarters via __ldcg and writes out. No second launch.

#define MAX_KLEN 11
#define WARPS_PER_CTA 15
#define XPITCH 33
#define HALO 128
#define NQ 4
#define BGMAX 4
#define KMAX 8192

__device__ int   g_ctr[BGMAX];          // unit counter (self-reset)
__device__ int   g_done[BGMAX];         // phase-1 CTA arrivals (self-reset)
__device__ int   g_done2[BGMAX];        // phase-2 CTA arrivals (self-reset)
__device__ float g_scr[(size_t)BGMAX * KMAX * NQ * 64];

__device__ __forceinline__ void red_add_release(int* p, int v) {
    asm volatile("red.release.gpu.global.add.s32 [%0], %1;"
                 :: "l"(p), "r"(v) : "memory");
}
__device__ __forceinline__ int ld_acquire(const int* p) {
    int v;
    asm volatile("ld.acquire.gpu.global.s32 %0, [%1];"
                 : "=r"(v) : "l"(p) : "memory");
    return v;
}

// ---------- fast path (all taps within halo bounds) ----------
template<int KLEN, int NB>
__device__ __forceinline__ void conv_block(
    const float* __restrict__ p, int dp,
    const float* __restrict__ w, float bs,
    float& mx, float& cnt)
{
    float Y[NB + KLEN - 1];
#pragma unroll
    for (int t = 0; t < NB + KLEN - 1; t++) Y[t] = p[t * dp];
#pragma unroll
    for (int i = 0; i < NB; i++) {
        float a = bs;
#pragma unroll
        for (int j = 0; j < KLEN; j++) a = fmaf(w[j], Y[i + j], a);
        mx = fmaxf(mx, a);
        cnt += (a > 0.0f) ? 1.0f : 0.0f;
    }
}

template<int KLEN>
__device__ __forceinline__ void conv_range(
    const float* __restrict__ xsl,
    int r, int pd, int mlo, int mhi, int d, int dp,
    const float* __restrict__ w, float bs,
    float& mx, float& cnt)
{
    int m0 = mlo;
    const float* p = xsl + (HALO + r - pd + m0 * d) * XPITCH;
    for (; m0 + 8 <= mhi; m0 += 8) {
        conv_block<KLEN, 8>(p, dp, w, bs, mx, cnt);
        p += 8 * dp;
    }
    if (m0 + 4 <= mhi) { conv_block<KLEN, 4>(p, dp, w, bs, mx, cnt); m0 += 4; p += 4 * dp; }
    if (m0 + 2 <= mhi) { conv_block<KLEN, 2>(p, dp, w, bs, mx, cnt); m0 += 2; p += 2 * dp; }
    if (m0 < mhi)      { conv_block<KLEN, 1>(p, dp, w, bs, mx, cnt); }
}

template<int KLEN>
__device__ __forceinline__ void process_unit(
    const float* __restrict__ xsl, int d, int pd, int ol, int q,
    const float* __restrict__ w, float bs, float& mx, float& cnt)
{
    const int dp = d * XPITCH;
    const int q0 = (ol - 1) / d;
    const int rr = (ol - 1) - q0 * d;
    if (d >= NQ) {
        for (int r = q; r < d; r += NQ) {
            const int M = (r <= rr) ? q0 + 1 : q0;   // = ceil((ol-r)/d)
            conv_range<KLEN>(xsl, r, pd, 0, M, d, dp, w, bs, mx, cnt);
        }
    } else {
        for (int r = 0; r < d; r++) {
            const int M = (r <= rr) ? q0 + 1 : q0;
            conv_range<KLEN>(xsl, r, pd, (q * M) >> 2, ((q + 1) * M) >> 2,
                             d, dp, w, bs, mx, cnt);
        }
    }
}

// ---------- clamped path (pad >= HALO): clamp row into the zero halos ----------
template<int KLEN, int NB>
__device__ __forceinline__ void conv_block_c(
    const float* __restrict__ xsl, int row0, int d, int rmax,
    const float* __restrict__ w, float bs,
    float& mx, float& cnt)
{
    float Y[NB + KLEN - 1];
#pragma unroll
    for (int t = 0; t < NB + KLEN - 1; t++) {
        int rr = row0 + t * d;
        rr = min(max(rr, 0), rmax);              // lands in zero halo if OOB
        Y[t] = xsl[rr * XPITCH];
    }
#pragma unroll
    for (int i = 0; i < NB; i++) {
        float a = bs;
#pragma unroll
        for (int j = 0; j < KLEN; j++) a = fmaf(w[j], Y[i + j], a);
        mx = fmaxf(mx, a);
        cnt += (a > 0.0f) ? 1.0f : 0.0f;
    }
}

template<int KLEN>
__device__ __forceinline__ void conv_range_c(
    const float* __restrict__ xsl,
    int r, int pd, int mlo, int mhi, int d, int rmax,
    const float* __restrict__ w, float bs,
    float& mx, float& cnt)
{
    int m0 = mlo;
    int row0 = HALO + r - pd + m0 * d;
    for (; m0 + 8 <= mhi; m0 += 8) {
        conv_block_c<KLEN, 8>(xsl, row0, d, rmax, w, bs, mx, cnt);
        row0 += 8 * d;
    }
    if (m0 + 4 <= mhi) { conv_block_c<KLEN, 4>(xsl, row0, d, rmax, w, bs, mx, cnt); m0 += 4; row0 += 4 * d; }
    if (m0 + 2 <= mhi) { conv_block_c<KLEN, 2>(xsl, row0, d, rmax, w, bs, mx, cnt); m0 += 2; row0 += 2 * d; }
    if (m0 < mhi)      { conv_block_c<KLEN, 1>(xsl, row0, d, rmax, w, bs, mx, cnt); }
}

template<int KLEN>
__device__ __forceinline__ void process_unit_c(
    const float* __restrict__ xsl, int d, int pd, int ol, int q, int T,
    const float* __restrict__ w, float bs, float& mx, float& cnt)
{
    const int rmax = 2 * HALO + T - 1;
    const int q0 = (ol - 1) / d;
    const int rr = (ol - 1) - q0 * d;
    if (d >= NQ) {
        for (int r = q; r < d; r += NQ) {
            const int M = (r <= rr) ? q0 + 1 : q0;
            conv_range_c<KLEN>(xsl, r, pd, 0, M, d, rmax, w, bs, mx, cnt);
        }
    } else {
        for (int r = 0; r < d; r++) {
            const int M = (r <= rr) ? q0 + 1 : q0;
            conv_range_c<KLEN>(xsl, r, pd, (q * M) >> 2, ((q + 1) * M) >> 2,
                               d, rmax, w, bs, mx, cnt);
        }
    }
}

__global__ void __launch_bounds__(32 * WARPS_PER_CTA, 2)
rf_main(const float* __restrict__ x,
        const float* __restrict__ w,
        const float* __restrict__ bias,
        const int*   __restrict__ dil,
        const int*   __restrict__ padr,
        const int*   __restrict__ olen,
        float* __restrict__ out,
        int B, int T, int K)
{
    extern __shared__ float xs[];                 // [(HALO+T+HALO)][XPITCH]
    const int lane = threadIdx.x & 31;
    const int warp = threadIdx.x >> 5;
    const int bg   = blockIdx.y;
    const int b0   = bg * 32;
    const int nb   = min(32, B - b0);
    const int nctas = gridDim.x;                  // CTAs in this batch group

    // Transposed fill with zero halos: coalesced LDG, conflict-free STS (33 odd).
    for (int bb = warp; bb < 32; bb += WARPS_PER_CTA) {
        const int bsafe = min(bb, nb - 1);
        for (int t = lane; t < HALO; t += 32) {
            xs[t * XPITCH + bb] = 0.0f;
            xs[(HALO + T + t) * XPITCH + bb] = 0.0f;
        }
        for (int t = lane; t < T; t += 32) {
            float v = x[(size_t)(b0 + bsafe) * T + t];
            xs[(HALO + t) * XPITCH + bb] = (bb < nb) ? v : 0.0f;
        }
    }
    __syncthreads();

    const float* xsl = xs + lane;
    const int nunits = K * NQ;

    // ---------------- Phase 1: conv partials ----------------
    for (;;) {
        int u = 0;
        if (lane == 0) u = atomicAdd(&g_ctr[bg], 1);
        u = __shfl_sync(0xFFFFFFFFu, u, 0);
        if (u >= nunits) break;

        const int k = u >> 2;
        const int q = u & (NQ - 1);
        const int   d  = dil[k];
        const int   pd = padr[k];
        const int   ol = olen[k];
        const float bv = bias[k];

        float wreg[MAX_KLEN];
#pragma unroll
        for (int j = 0; j < MAX_KLEN; j++)
            wreg[j] = __ldg(&w[(size_t)k * MAX_KLEN + j]);

        float mx  = -CUDART_INF_F;
        float cnt = 0.0f;

        const int klen = (wreg[9] != 0.0f || wreg[10] != 0.0f) ? 11
                       : (wreg[7] != 0.0f || wreg[8] != 0.0f) ? 9 : 7;
        const bool safe = (d >= 1) && (pd < HALO) &&
                          ((ol - 1) - pd + (long long)(klen - 1) * d < T + HALO);

        if (safe) {
            if (klen == 11)      process_unit<11>(xsl, d, pd, ol, q, wreg, bv, mx, cnt);
            else if (klen == 9)  process_unit<9>(xsl, d, pd, ol, q, wreg, bv, mx, cnt);
            else                 process_unit<7>(xsl, d, pd, ol, q, wreg, bv, mx, cnt);
        } else if (d >= 1) {
            if (klen == 11)      process_unit_c<11>(xsl, d, pd, ol, q, T, wreg, bv, mx, cnt);
            else if (klen == 9)  process_unit_c<9>(xsl, d, pd, ol, q, T, wreg, bv, mx, cnt);
            else                 process_unit_c<7>(xsl, d, pd, ol, q, T, wreg, bv, mx, cnt);
        }

        float* s = g_scr + ((size_t)bg * KMAX * NQ + u) * 64;
        __stcg(&s[lane], mx);                     // L2-direct: no fence needed
        __stcg(&s[32 + lane], cnt);
    }

    // ---------------- Grid-wide barrier (one resident wave guaranteed) -------
    __syncthreads();
    if (threadIdx.x == 0) {
        red_add_release(&g_done[bg], 1);          // releases our stcg stores
        while (ld_acquire(&g_done[bg]) < nctas) __nanosleep(64);
    }
    __syncthreads();

    // ---------------- Phase 2: combine quarters, write out ----------------
    for (int k = blockIdx.x * WARPS_PER_CTA + warp; k < K;
         k += nctas * WARPS_PER_CTA) {
        const float* sb = g_scr + ((size_t)bg * KMAX + k) * NQ * 64;
        float m0 = __ldcg(&sb[lane]),       c0 = __ldcg(&sb[32 + lane]);
        float m1 = __ldcg(&sb[64 + lane]),  c1 = __ldcg(&sb[96 + lane]);
        float m2 = __ldcg(&sb[128 + lane]), c2 = __ldcg(&sb[160 + lane]);
        float m3 = __ldcg(&sb[192 + lane]), c3 = __ldcg(&sb[224 + lane]);
        if (lane < nb) {
            float* o = out + (size_t)(b0 + lane) * 2 * K + 2 * k;
            o[0] = fmaxf(fmaxf(m0, m1), fmaxf(m2, m3));
            o[1] = ((c0 + c1) + (c2 + c3)) / (float)olen[k];
        }
    }

    // ---------------- Counter reset for graph replay ----------------
    __syncthreads();
    if (threadIdx.x == 0) {
        int dn = atomicAdd(&g_done2[bg], 1);
        if (dn == nctas - 1) {                    // last CTA: everyone is past
            g_ctr[bg]   = 0;                      //   the g_done spin and fin
            g_done[bg]  = 0;
            g_done2[bg] = 0;
        }
    }
}

extern "C" void kernel_launch(void* const* d_in, const int* in_sizes, int n_in,
                              void* d_out, int out_size) {
    const float* x    = (const float*)d_in[0];
    const float* w    = (const float*)d_in[1];
    const float* bias = (const float*)d_in[2];
    const int*   dil  = (const int*)d_in[3];
    const int*   padr = (const int*)d_in[4];
    const int*   olen = (const int*)d_in[5];
    float* out = (float*)d_out;

    const int K = in_sizes[2];                 // bias element count
    const int B = out_size / (2 * K);
    const int T = in_sizes[0] / B;
    const int nbg = (B + 31) / 32;             // batch groups (<= BGMAX)

    const size_t smem = (size_t)(2 * HALO + T) * XPITCH * sizeof(float);
    cudaFuncSetAttribute(rf_main,
                         cudaFuncAttributeMaxDynamicSharedMemorySize,
                         (int)smem);

    // Exactly one resident wave: 2 CTAs/SM x 148 SMs, split across batch groups.
    int ctas_per_bg = 296 / nbg;
    dim3 grid(ctas_per_bg, nbg);
    rf_main<<<grid, 32 * WARPS_PER_CTA, smem>>>(x, w, bias, dil, padr, olen,
                                                out, B, T, K);
}